// round 6
// baseline (speedup 1.0000x reference)
#include <cuda_runtime.h>

// LearnAdjacency: LayerNorm over a size-1 trailing axis maps everything to
// ln_beta (x - mean(x) == 0 for a singleton axis); row-softmax of a constant
// row gives 1/(N + 1e-8) == 1/256 exactly in fp32 (256.0f + 1e-8f == 256.0f).
// Output = 524288 floats of 0.00390625 — a 2 MB constant fill that sinks into
// L2. Measured across grid shapes (512x256x1, 128x256x4) the kernel is pinned
// at ~3.8-4.1us: launch/drain + DVFS floor, not issue or memory bound. This
// variant takes the midpoint (256 CTAs, 2 independent STG.128/thread) to
// confirm the floor; no further kernel-side lever exists below one launch.

__global__ __launch_bounds__(256, 2)
void fill_const_kernel(float4* __restrict__ out, float v) {
    const float4 val = make_float4(v, v, v, v);
    // Coalesced: consecutive threads -> consecutive float4s within each chunk.
    unsigned base = blockIdx.x * 512u + threadIdx.x;
    out[base]       = val;
    out[base + 256] = val;
}

extern "C" void kernel_launch(void* const* d_in, const int* in_sizes, int n_in,
                              void* d_out, int out_size) {
    (void)d_in; (void)in_sizes; (void)n_in;
    const int N = 256;
    const float v = 1.0f / ((float)N + 1e-8f);   // == 0.00390625f in fp32

    // out_size = 524288 floats = 131072 float4 = 256 blocks * 256 threads * 2.
    int n_vec = out_size / 4;
    int blocks = n_vec / (256 * 2);              // 256, exact fit (no tail)
    fill_const_kernel<<<blocks, 256>>>((float4*)d_out, v);
}

// round 8
// speedup vs baseline: 1.0064x; 1.0064x over previous
#include <cuda_runtime.h>

// LearnAdjacency — final kernel (resubmission; R7 bench failure was a broker
// container error, not a kernel error — this exact source passed at ~5.0us).
//
// Algebra: the reference applies LayerNorm over a trailing axis of SIZE 1,
// so x - mean(x) == 0 exactly and y == ln_beta (a constant) for every
// element; the upstream pairwise-L1 / relu stage is dead code. Row-softmax
// of a constant row gives 1/(N + 1e-8); with N=256 in fp32,
// 256.0f + 1e-8f == 256.0f, so every output element is exactly
// 1/256 = 0.00390625 (0x3B800000). rel_err == 0.0 verified (R2/R3/R5/R6).
//
// The task is therefore a 2 MB constant fill. Measured across grid shapes
// (512x256x1 / 256x256x2 / 128x256x4) end-to-end is pinned at 5.0-5.2us:
// all pipes <1%, DRAM 0% (stores sink into L2), issue <6% — this is the
// one-launch + graph-replay floor. One launch is the provable minimum
// (0x3B800000 has no repeating byte pattern -> no memset path; the output
// buffer is poisoned -> must be fully written). Locked configuration:
// 128 CTAs (one per SM, single wave) x 256 threads x 4 independent STG.128
// per thread, exact fit, no loop, no predicate.

__global__ __launch_bounds__(256, 1)
void fill_const_kernel(float4* __restrict__ out, float v) {
    const float4 val = make_float4(v, v, v, v);
    // Coalesced: consecutive threads -> consecutive float4s within each chunk.
    unsigned base = blockIdx.x * 1024u + threadIdx.x;
    out[base]        = val;
    out[base + 256]  = val;
    out[base + 512]  = val;
    out[base + 768]  = val;
}

extern "C" void kernel_launch(void* const* d_in, const int* in_sizes, int n_in,
                              void* d_out, int out_size) {
    (void)d_in; (void)in_sizes; (void)n_in;
    const int N = 256;
    const float v = 1.0f / ((float)N + 1e-8f);   // == 0.00390625f in fp32

    // out_size = 524288 floats = 131072 float4 = 128 blocks * 256 threads * 4.
    int n_vec = out_size / 4;
    int blocks = n_vec / (256 * 4);              // 128, exact fit (no tail)
    fill_const_kernel<<<blocks, 256>>>((float4*)d_out, v);
}